// round 1
// baseline (speedup 1.0000x reference)
#include <cuda_runtime.h>
#include <cuda_bf16.h>

// Problem constants
#define B_   4
#define N_   4096
#define D_   1024
#define H_   16
#define DH_  64
#define L_   64                  // scan chunk length
#define NCH_ (N_ / L_)           // 64 chunks
#define M_   (B_ * N_)           // 16384 tokens

// Scratch (allocation-free rule: __device__ globals)
__device__ float g_o[B_ * N_ * D_];          // 64 MB: scan output -> normalized activations
__device__ float g_carry[B_ * NCH_ * D_];    // per-chunk carries
__device__ float g_lam[H_];
__device__ float g_c[H_];

// exact-ish integer power by squaring (few roundings, no libm error surprises)
__device__ __forceinline__ float pow_int(float base, int e) {
    float p = 1.0f;
    float b = base;
    while (e) {
        if (e & 1) p *= b;
        b *= b;
        e >>= 1;
    }
    return p;
}

// ---------------------------------------------------------------------------
// Kernel 0: per-head constants lam_h = sigmoid(log_decay_h), c_h = q_h . k_h
// ---------------------------------------------------------------------------
__global__ void k_init(const float* __restrict__ q, const float* __restrict__ k,
                       const float* __restrict__ log_decay) {
    int h = threadIdx.x;
    if (h >= H_) return;
    float a = log_decay[h];
    g_lam[h] = 1.0f / (1.0f + expf(-a));
    float c = 0.0f;
    const float* qh = q + h * DH_;
    const float* kh = k + h * DH_;
    #pragma unroll 16
    for (int j = 0; j < DH_; j++) c += qh[j] * kh[j];
    g_c[h] = c;
}

// ---------------------------------------------------------------------------
// Phase A: local scans per chunk. grid = B*NCH blocks, 1024 threads (one per d)
// ---------------------------------------------------------------------------
__global__ __launch_bounds__(1024) void k_scan_local(const float* __restrict__ x) {
    int blk = blockIdx.x;
    int b = blk / NCH_;
    int c = blk % NCH_;
    int d = threadIdx.x;
    float lam = g_lam[d >> 6];

    int base = (b * N_ + c * L_) * D_ + d;
    float s = 0.0f;
    #pragma unroll 8
    for (int t = 0; t < L_; t++) {
        s = fmaf(lam, s, x[base + t * D_]);
        g_o[base + t * D_] = s;
    }
    g_carry[(b * NCH_ + c) * D_ + d] = s;
}

// ---------------------------------------------------------------------------
// Phase B: sequential carry combine across chunks (inclusive prefix with lam^L)
// grid covers B*D threads
// ---------------------------------------------------------------------------
__global__ __launch_bounds__(256) void k_scan_combine() {
    int idx = blockIdx.x * blockDim.x + threadIdx.x;   // [0, B*D)
    int b = idx / D_;
    int d = idx % D_;
    float lam = g_lam[d >> 6];
    float lamL = pow_int(lam, L_);
    float P = 0.0f;
    int base = b * NCH_ * D_ + d;
    #pragma unroll 8
    for (int c = 0; c < NCH_; c++) {
        P = fmaf(lamL, P, g_carry[base + c * D_]);
        g_carry[base + c * D_] = P;
    }
}

// ---------------------------------------------------------------------------
// Phase C: carry fixup + scale by c_h + RMSNorm. One block per token.
// 256 threads, 4 channels (float4) per thread.
// ---------------------------------------------------------------------------
__global__ __launch_bounds__(256) void k_fix_norm(const float* __restrict__ norm_weight) {
    int tok = blockIdx.x;            // [0, B*N)
    int b = tok / N_;
    int n = tok % N_;
    int chunk = n >> 6;
    int tl = n & (L_ - 1);
    int tid = threadIdx.x;
    int d0 = tid * 4;
    int h = d0 >> 6;                 // 4 channels stay inside one head

    float lam = g_lam[h];
    float ch  = g_c[h];

    float4 v = *(const float4*)&g_o[tok * D_ + d0];
    if (chunk > 0) {
        float lp = pow_int(lam, tl + 1);
        float4 cr = *(const float4*)&g_carry[(b * NCH_ + (chunk - 1)) * D_ + d0];
        v.x = fmaf(lp, cr.x, v.x);
        v.y = fmaf(lp, cr.y, v.y);
        v.z = fmaf(lp, cr.z, v.z);
        v.w = fmaf(lp, cr.w, v.w);
    }
    v.x *= ch; v.y *= ch; v.z *= ch; v.w *= ch;

    // RMS over the 1024 channels of this token
    float ss = v.x * v.x + v.y * v.y + v.z * v.z + v.w * v.w;
    #pragma unroll
    for (int o = 16; o > 0; o >>= 1) ss += __shfl_xor_sync(0xFFFFFFFFu, ss, o);

    __shared__ float red[8];
    __shared__ float s_rstd;
    int lane = tid & 31, wid = tid >> 5;
    if (lane == 0) red[wid] = ss;
    __syncthreads();
    if (tid == 0) {
        float t = 0.0f;
        #pragma unroll
        for (int i = 0; i < 8; i++) t += red[i];
        s_rstd = rsqrtf(t * (1.0f / (float)D_) + 1e-6f);
    }
    __syncthreads();
    float rstd = s_rstd;

    float4 w = *(const float4*)&norm_weight[d0];
    v.x *= rstd * w.x; v.y *= rstd * w.y; v.z *= rstd * w.z; v.w *= rstd * w.w;
    *(float4*)&g_o[tok * D_ + d0] = v;
}

// ---------------------------------------------------------------------------
// GEMM: C[m,j] = sum_d A[m,d] * W[j,d]   (A = g_o 16384x1024, W = o_w 1024x1024)
// Classic SGEMM: 128x128 block tile, BK=16, 256 threads, 8x8 per thread.
// ---------------------------------------------------------------------------
#define BM 128
#define BN 128
#define BK 16
#define TM 8
#define TN 8

__global__ __launch_bounds__(256) void k_gemm(const float* __restrict__ A,
                                              const float* __restrict__ W,
                                              float* __restrict__ C) {
    __shared__ float As[BK][BM];
    __shared__ float Ws[BK][BN];

    const int bm = blockIdx.y * BM;
    const int bn = blockIdx.x * BN;
    const int tid = threadIdx.x;

    const int row0 = (tid / 16) * TM;   // 0..120
    const int col0 = (tid % 16) * TN;   // 0..120

    float acc[TM][TN];
    #pragma unroll
    for (int i = 0; i < TM; i++)
        #pragma unroll
        for (int j = 0; j < TN; j++) acc[i][j] = 0.0f;

    const int K = D_;
    for (int k0 = 0; k0 < K; k0 += BK) {
        // Each tile: 128 rows x 16 cols = 512 float4. 2 float4 per thread (A and W).
        #pragma unroll
        for (int i = 0; i < 2; i++) {
            int f = tid + i * 256;        // [0,512)
            int r = f >> 2;               // row within tile
            int kq = (f & 3) * 4;         // k-quad start
            float4 va = *(const float4*)&A[(bm + r) * K + k0 + kq];
            As[kq + 0][r] = va.x; As[kq + 1][r] = va.y;
            As[kq + 2][r] = va.z; As[kq + 3][r] = va.w;
            float4 vw = *(const float4*)&W[(bn + r) * K + k0 + kq];
            Ws[kq + 0][r] = vw.x; Ws[kq + 1][r] = vw.y;
            Ws[kq + 2][r] = vw.z; Ws[kq + 3][r] = vw.w;
        }
        __syncthreads();

        #pragma unroll
        for (int kk = 0; kk < BK; kk++) {
            float a[TM], bb[TN];
            #pragma unroll
            for (int i = 0; i < TM; i++) a[i] = As[kk][row0 + i];
            #pragma unroll
            for (int j = 0; j < TN; j++) bb[j] = Ws[kk][col0 + j];
            #pragma unroll
            for (int i = 0; i < TM; i++)
                #pragma unroll
                for (int j = 0; j < TN; j++)
                    acc[i][j] = fmaf(a[i], bb[j], acc[i][j]);
        }
        __syncthreads();
    }

    #pragma unroll
    for (int i = 0; i < TM; i++) {
        float* crow = &C[(bm + row0 + i) * D_ + bn + col0];
        #pragma unroll
        for (int j = 0; j < TN; j += 4) {
            float4 v = make_float4(acc[i][j], acc[i][j + 1], acc[i][j + 2], acc[i][j + 3]);
            *(float4*)&crow[j] = v;
        }
    }
}

// ---------------------------------------------------------------------------
// launch
// ---------------------------------------------------------------------------
extern "C" void kernel_launch(void* const* d_in, const int* in_sizes, int n_in,
                              void* d_out, int out_size) {
    const float* x           = (const float*)d_in[0];
    const float* q           = (const float*)d_in[1];
    const float* k           = (const float*)d_in[2];
    const float* log_decay   = (const float*)d_in[3];
    const float* norm_weight = (const float*)d_in[4];
    const float* o_w         = (const float*)d_in[5];
    float* out = (float*)d_out;

    k_init<<<1, 32>>>(q, k, log_decay);
    k_scan_local<<<B_ * NCH_, 1024>>>(x);
    k_scan_combine<<<(B_ * D_) / 256, 256>>>();
    k_fix_norm<<<M_, 256>>>(norm_weight);

    float* A;
    cudaGetSymbolAddress((void**)&A, g_o);
    dim3 grid(D_ / BN, M_ / BM);
    k_gemm<<<grid, 256>>>(A, o_w, out);
}

// round 3
// speedup vs baseline: 2.4455x; 2.4455x over previous
#include <cuda_runtime.h>
#include <cuda_bf16.h>
#include <cstdint>

// Problem constants
#define B_   4
#define N_   4096
#define D_   1024
#define H_   16
#define DH_  64
#define L_   64
#define NCH_ (N_ / L_)
#define M_   (B_ * N_)           // 16384 tokens

// Scratch (__device__ globals; no allocation allowed)
__device__ float g_o[B_ * N_ * D_];
__device__ float g_carry[B_ * NCH_ * D_];
__device__ float g_lam[H_];
__device__ float g_c[H_];
__device__ __nv_bfloat16 g_a_hi[M_ * D_];
__device__ __nv_bfloat16 g_a_lo[M_ * D_];
__device__ __nv_bfloat16 g_w_hi[D_ * D_];
__device__ __nv_bfloat16 g_w_lo[D_ * D_];

__device__ __forceinline__ float pow_int(float base, int e) {
    float p = 1.0f, b = base;
    while (e) { if (e & 1) p *= b; b *= b; e >>= 1; }
    return p;
}

__device__ __forceinline__ uint32_t smem_u32(const void* p) {
    uint32_t a;
    asm("{ .reg .u64 t; cvta.to.shared.u64 t, %1; cvt.u32.u64 %0, t; }" : "=r"(a) : "l"(p));
    return a;
}

#define CP_ASYNC16(dst, src) \
    asm volatile("cp.async.cg.shared.global [%0], [%1], 16;" :: "r"(dst), "l"(src) : "memory")
#define CP_COMMIT() asm volatile("cp.async.commit_group;" ::: "memory")
#define CP_WAIT2()  asm volatile("cp.async.wait_group 2;" ::: "memory")

#define LDSM4(r0, r1, r2, r3, addr) \
    asm volatile("ldmatrix.sync.aligned.m8n8.x4.shared.b16 {%0,%1,%2,%3}, [%4];" \
                 : "=r"(r0), "=r"(r1), "=r"(r2), "=r"(r3) : "r"(addr))

#define MMA_BF16(d, a, b) \
    asm volatile("mma.sync.aligned.m16n8k16.row.col.f32.bf16.bf16.f32 " \
                 "{%0,%1,%2,%3}, {%4,%5,%6,%7}, {%8,%9}, {%0,%1,%2,%3};" \
                 : "+f"((d)[0]), "+f"((d)[1]), "+f"((d)[2]), "+f"((d)[3]) \
                 : "r"((a)[0]), "r"((a)[1]), "r"((a)[2]), "r"((a)[3]), \
                   "r"((b)[0]), "r"((b)[1]))

// ============================ scan phases ============================
__global__ void k_init(const float* __restrict__ q, const float* __restrict__ k,
                       const float* __restrict__ log_decay) {
    int h = threadIdx.x;
    if (h >= H_) return;
    float a = log_decay[h];
    g_lam[h] = 1.0f / (1.0f + expf(-a));
    float c = 0.0f;
    const float* qh = q + h * DH_;
    const float* kh = k + h * DH_;
    #pragma unroll 16
    for (int j = 0; j < DH_; j++) c += qh[j] * kh[j];
    g_c[h] = c;
}

__global__ __launch_bounds__(1024) void k_scan_local(const float* __restrict__ x) {
    int blk = blockIdx.x;
    int b = blk / NCH_;
    int c = blk % NCH_;
    int d = threadIdx.x;
    float lam = g_lam[d >> 6];
    int base = (b * N_ + c * L_) * D_ + d;
    float s = 0.0f;
    #pragma unroll 8
    for (int t = 0; t < L_; t++) {
        s = fmaf(lam, s, x[base + t * D_]);
        g_o[base + t * D_] = s;
    }
    g_carry[(b * NCH_ + c) * D_ + d] = s;
}

__global__ __launch_bounds__(256) void k_scan_combine() {
    int idx = blockIdx.x * blockDim.x + threadIdx.x;
    int b = idx / D_;
    int d = idx % D_;
    float lam = g_lam[d >> 6];
    float lamL = pow_int(lam, L_);
    float P = 0.0f;
    int base = b * NCH_ * D_ + d;
    #pragma unroll 8
    for (int c = 0; c < NCH_; c++) {
        P = fmaf(lamL, P, g_carry[base + c * D_]);
        g_carry[base + c * D_] = P;
    }
}

__global__ __launch_bounds__(256) void k_fix_norm(const float* __restrict__ norm_weight) {
    int tok = blockIdx.x;
    int b = tok / N_;
    int n = tok % N_;
    int chunk = n >> 6;
    int tl = n & (L_ - 1);
    int tid = threadIdx.x;
    int d0 = tid * 4;
    int h = d0 >> 6;

    float lam = g_lam[h];
    float ch  = g_c[h];

    float4 v = *(const float4*)&g_o[(size_t)tok * D_ + d0];
    if (chunk > 0) {
        float lp = pow_int(lam, tl + 1);
        float4 cr = *(const float4*)&g_carry[(b * NCH_ + (chunk - 1)) * D_ + d0];
        v.x = fmaf(lp, cr.x, v.x);
        v.y = fmaf(lp, cr.y, v.y);
        v.z = fmaf(lp, cr.z, v.z);
        v.w = fmaf(lp, cr.w, v.w);
    }
    v.x *= ch; v.y *= ch; v.z *= ch; v.w *= ch;

    float ss = v.x * v.x + v.y * v.y + v.z * v.z + v.w * v.w;
    #pragma unroll
    for (int o = 16; o > 0; o >>= 1) ss += __shfl_xor_sync(0xFFFFFFFFu, ss, o);

    __shared__ float red[8];
    __shared__ float s_rstd;
    int lane = tid & 31, wid = tid >> 5;
    if (lane == 0) red[wid] = ss;
    __syncthreads();
    if (tid == 0) {
        float t = 0.0f;
        #pragma unroll
        for (int i = 0; i < 8; i++) t += red[i];
        s_rstd = rsqrtf(t * (1.0f / (float)D_) + 1e-6f);
    }
    __syncthreads();
    float rstd = s_rstd;

    float4 w = *(const float4*)&norm_weight[d0];
    float a0 = v.x * rstd * w.x, a1 = v.y * rstd * w.y;
    float a2 = v.z * rstd * w.z, a3 = v.w * rstd * w.w;

    __nv_bfloat16 h0 = __float2bfloat16(a0), h1 = __float2bfloat16(a1);
    __nv_bfloat16 h2 = __float2bfloat16(a2), h3 = __float2bfloat16(a3);
    __nv_bfloat16 l0 = __float2bfloat16(a0 - __bfloat162float(h0));
    __nv_bfloat16 l1 = __float2bfloat16(a1 - __bfloat162float(h1));
    __nv_bfloat16 l2 = __float2bfloat16(a2 - __bfloat162float(h2));
    __nv_bfloat16 l3 = __float2bfloat16(a3 - __bfloat162float(h3));

    size_t off = (size_t)tok * D_ + d0;
    __nv_bfloat162 ph0; ph0.x = h0; ph0.y = h1;
    __nv_bfloat162 ph1; ph1.x = h2; ph1.y = h3;
    __nv_bfloat162 pl0; pl0.x = l0; pl0.y = l1;
    __nv_bfloat162 pl1; pl1.x = l2; pl1.y = l3;
    *(__nv_bfloat162*)&g_a_hi[off]     = ph0;
    *(__nv_bfloat162*)&g_a_hi[off + 2] = ph1;
    *(__nv_bfloat162*)&g_a_lo[off]     = pl0;
    *(__nv_bfloat162*)&g_a_lo[off + 2] = pl1;
}

__global__ __launch_bounds__(256) void k_prep_w(const float* __restrict__ w) {
    int idx = blockIdx.x * blockDim.x + threadIdx.x;
    size_t off = (size_t)idx * 4;
    float4 v = *(const float4*)&w[off];
    __nv_bfloat16 h0 = __float2bfloat16(v.x), h1 = __float2bfloat16(v.y);
    __nv_bfloat16 h2 = __float2bfloat16(v.z), h3 = __float2bfloat16(v.w);
    __nv_bfloat16 l0 = __float2bfloat16(v.x - __bfloat162float(h0));
    __nv_bfloat16 l1 = __float2bfloat16(v.y - __bfloat162float(h1));
    __nv_bfloat16 l2 = __float2bfloat16(v.z - __bfloat162float(h2));
    __nv_bfloat16 l3 = __float2bfloat16(v.w - __bfloat162float(h3));
    __nv_bfloat162 ph0; ph0.x = h0; ph0.y = h1;
    __nv_bfloat162 ph1; ph1.x = h2; ph1.y = h3;
    __nv_bfloat162 pl0; pl0.x = l0; pl0.y = l1;
    __nv_bfloat162 pl1; pl1.x = l2; pl1.y = l3;
    *(__nv_bfloat162*)&g_w_hi[off]     = ph0;
    *(__nv_bfloat162*)&g_w_hi[off + 2] = ph1;
    *(__nv_bfloat162*)&g_w_lo[off]     = pl0;
    *(__nv_bfloat162*)&g_w_lo[off + 2] = pl1;
}

// ============================ HMMA GEMM ============================
// C[16384,1024] = Ahi*Whi^T + Alo*Whi^T + Ahi*Wlo^T   (all K-major bf16)
// CTA 128x128, BK=64, 8 warps (2 n-col x 4 m-row), warp tile 32x64.
#define GM 128
#define GN 128
#define KS 64
#define STG 4
#define NITER 48                               // 3 passes * 16 k-stages
#define STAGE_BYTES 32768                      // A 16KB + B 16KB
#define SMEM_GEMM_TOTAL (STG * STAGE_BYTES)    // 128KB

// SW128 swizzle within a 128-byte row block
#define SMEM_SWZ(off) ((off) ^ (((off) >> 3) & 0x70))

__device__ __forceinline__ void load_stage(uint32_t smem_base, int round, int bm, int bn, int tid) {
    int pass = round >> 4;                 // 0: hi*hi, 1: lo*hi, 2: hi*lo
    int k0 = (round & 15) * KS;
    const __nv_bfloat16* Asrc = (pass == 1) ? g_a_lo : g_a_hi;
    const __nv_bfloat16* Wsrc = (pass == 2) ? g_w_lo : g_w_hi;
    uint32_t sA = smem_base + (round & (STG - 1)) * STAGE_BYTES;
    uint32_t sB = sA + 16384;
    #pragma unroll
    for (int i = 0; i < 8; i++) {
        int idx = i * 256 + tid;           // [0, 2048)
        if (idx < 1024) {                  // A: 128 rows x 8 16B-chunks
            int r = idx >> 3, kc = idx & 7;
            const __nv_bfloat16* g = Asrc + (size_t)(bm + r) * D_ + k0 + kc * 8;
            CP_ASYNC16(sA + SMEM_SWZ(r * 128 + kc * 16), g);
        } else {                           // B: 128 rows x 8 chunks
            int c = idx - 1024;
            int r = c >> 3, kc = c & 7;
            const __nv_bfloat16* g = Wsrc + (size_t)(bn + r) * D_ + k0 + kc * 8;
            CP_ASYNC16(sB + SMEM_SWZ(r * 128 + kc * 16), g);
        }
    }
}

__global__ __launch_bounds__(256, 1) void k_gemm_mma(float* __restrict__ C) {
    extern __shared__ char smem[];
    uint32_t sb = smem_u32(smem);
    const int tid  = threadIdx.x;
    const int wid  = tid >> 5;
    const int lane = tid & 31;
    const int wm   = wid >> 1;          // 0..3 (M)
    const int wn   = wid & 1;           // 0..1 (N)
    const int bm   = blockIdx.y * GM;
    const int bn   = blockIdx.x * GN;

    // ldmatrix per-lane geometry
    const int t7 = lane & 7;            // row within 8x8 matrix
    const int q  = lane >> 3;           // which matrix this lane addresses
    // A: x4 matrices in mma order: (m0,k0),(m+8,k0),(m0,k8),(m+8,k8)
    const int a_row = wm * 32 + (q & 1) * 8 + t7;          // + im*16
    const int a_cq  = q >> 1;                               // k8 select
    // B: x4 matrices: (n0,k0),(n0,k8),(n+8,k0),(n+8,k8) -> b[2jj][0],b[2jj][1],b[2jj+1][0],b[2jj+1][1]
    const int b_row = wn * 64 + (q >> 1) * 8 + t7;         // + jj*16
    const int b_cq  = q & 1;

    float acc[2][8][4];
    #pragma unroll
    for (int im = 0; im < 2; im++)
        #pragma unroll
        for (int j = 0; j < 8; j++)
            #pragma unroll
            for (int e = 0; e < 4; e++) acc[im][j][e] = 0.0f;

    // prologue
    #pragma unroll
    for (int r = 0; r < STG - 1; r++) { load_stage(sb, r, bm, bn, tid); CP_COMMIT(); }

    for (int i = 0; i < NITER; i++) {
        CP_WAIT2();
        __syncthreads();
        int j = i + STG - 1;
        if (j < NITER) load_stage(sb, j, bm, bn, tid);
        CP_COMMIT();

        uint32_t base  = sb + (i & (STG - 1)) * STAGE_BYTES;
        uint32_t baseB = base + 16384;
        #pragma unroll
        for (int ks = 0; ks < 4; ks++) {
            uint32_t af[2][4];
            #pragma unroll
            for (int im = 0; im < 2; im++) {
                uint32_t addr = base + (a_row + im * 16) * 128
                              + (((ks * 2 + a_cq) ^ t7) << 4);
                LDSM4(af[im][0], af[im][1], af[im][2], af[im][3], addr);
            }
            uint32_t bf[8][2];
            #pragma unroll
            for (int jj = 0; jj < 4; jj++) {
                uint32_t addr = baseB + (b_row + jj * 16) * 128
                              + (((ks * 2 + b_cq) ^ t7) << 4);
                LDSM4(bf[2 * jj][0], bf[2 * jj][1], bf[2 * jj + 1][0], bf[2 * jj + 1][1], addr);
            }
            #pragma unroll
            for (int im = 0; im < 2; im++)
                #pragma unroll
                for (int jt = 0; jt < 8; jt++)
                    MMA_BF16(acc[im][jt], af[im], bf[jt]);
        }
    }

    // epilogue: direct fp32 stores
    #pragma unroll
    for (int im = 0; im < 2; im++) {
        int r0 = bm + wm * 32 + im * 16 + (lane >> 2);
        #pragma unroll
        for (int jt = 0; jt < 8; jt++) {
            int c = bn + wn * 64 + jt * 8 + (lane & 3) * 2;
            float2 v0 = make_float2(acc[im][jt][0], acc[im][jt][1]);
            float2 v1 = make_float2(acc[im][jt][2], acc[im][jt][3]);
            *(float2*)&C[(size_t)r0 * D_ + c]       = v0;
            *(float2*)&C[(size_t)(r0 + 8) * D_ + c] = v1;
        }
    }
}

// ============================ launch ============================
extern "C" void kernel_launch(void* const* d_in, const int* in_sizes, int n_in,
                              void* d_out, int out_size) {
    const float* x           = (const float*)d_in[0];
    const float* q           = (const float*)d_in[1];
    const float* k           = (const float*)d_in[2];
    const float* log_decay   = (const float*)d_in[3];
    const float* norm_weight = (const float*)d_in[4];
    const float* o_w         = (const float*)d_in[5];
    float* out = (float*)d_out;

    k_init<<<1, 32>>>(q, k, log_decay);
    k_prep_w<<<(D_ * D_ / 4) / 256, 256>>>(o_w);
    k_scan_local<<<B_ * NCH_, 1024>>>(x);
    k_scan_combine<<<(B_ * D_) / 256, 256>>>();
    k_fix_norm<<<M_, 256>>>(norm_weight);

    cudaFuncSetAttribute(k_gemm_mma, cudaFuncAttributeMaxDynamicSharedMemorySize,
                         SMEM_GEMM_TOTAL);
    dim3 grid(D_ / GN, M_ / GM);
    k_gemm_mma<<<grid, 256, SMEM_GEMM_TOTAL>>>(out);
}

// round 4
// speedup vs baseline: 2.9593x; 1.2101x over previous
#include <cuda_runtime.h>
#include <cuda_bf16.h>
#include <cstdint>

// Problem constants
#define B_   4
#define N_   4096
#define D_   1024
#define H_   16
#define DH_  64
#define L_   64
#define NCH_ (N_ / L_)
#define M_   (B_ * N_)           // 16384 tokens

// Scratch (__device__ globals; no allocation allowed)
__device__ float g_o[B_ * N_ * D_];
__device__ float g_carry[B_ * NCH_ * D_];
__device__ float g_lam[H_];
__device__ float g_c[H_];
__device__ __nv_bfloat16 g_a_hi[M_ * D_];
__device__ __nv_bfloat16 g_a_lo[M_ * D_];
__device__ __nv_bfloat16 g_w_hi[D_ * D_];
__device__ __nv_bfloat16 g_w_lo[D_ * D_];

__device__ __forceinline__ float pow_int(float base, int e) {
    float p = 1.0f, b = base;
    while (e) { if (e & 1) p *= b; b *= b; e >>= 1; }
    return p;
}

__device__ __forceinline__ uint32_t smem_u32(const void* p) {
    uint32_t a;
    asm("{ .reg .u64 t; cvta.to.shared.u64 t, %1; cvt.u32.u64 %0, t; }" : "=r"(a) : "l"(p));
    return a;
}

#define CP_ASYNC16(dst, src) \
    asm volatile("cp.async.cg.shared.global [%0], [%1], 16;" :: "r"(dst), "l"(src) : "memory")
#define CP_COMMIT() asm volatile("cp.async.commit_group;" ::: "memory")
#define CP_WAIT1()  asm volatile("cp.async.wait_group 1;" ::: "memory")

#define LDSM4(r0, r1, r2, r3, addr) \
    asm volatile("ldmatrix.sync.aligned.m8n8.x4.shared.b16 {%0,%1,%2,%3}, [%4];" \
                 : "=r"(r0), "=r"(r1), "=r"(r2), "=r"(r3) : "r"(addr))

#define MMA_BF16(d, a, b) \
    asm volatile("mma.sync.aligned.m16n8k16.row.col.f32.bf16.bf16.f32 " \
                 "{%0,%1,%2,%3}, {%4,%5,%6,%7}, {%8,%9}, {%0,%1,%2,%3};" \
                 : "+f"((d)[0]), "+f"((d)[1]), "+f"((d)[2]), "+f"((d)[3]) \
                 : "r"((a)[0]), "r"((a)[1]), "r"((a)[2]), "r"((a)[3]), \
                   "r"((b)[0]), "r"((b)[1]))

// ============================ scan phases ============================
__global__ void k_init(const float* __restrict__ q, const float* __restrict__ k,
                       const float* __restrict__ log_decay) {
    int h = threadIdx.x;
    if (h >= H_) return;
    float a = log_decay[h];
    g_lam[h] = 1.0f / (1.0f + expf(-a));
    float c = 0.0f;
    const float* qh = q + h * DH_;
    const float* kh = k + h * DH_;
    #pragma unroll 16
    for (int j = 0; j < DH_; j++) c += qh[j] * kh[j];
    g_c[h] = c;
}

__global__ __launch_bounds__(1024) void k_scan_local(const float* __restrict__ x) {
    int blk = blockIdx.x;
    int b = blk / NCH_;
    int c = blk % NCH_;
    int d = threadIdx.x;
    float lam = g_lam[d >> 6];
    int base = (b * N_ + c * L_) * D_ + d;
    float s = 0.0f;
    #pragma unroll 8
    for (int t = 0; t < L_; t++) {
        s = fmaf(lam, s, x[base + t * D_]);
        g_o[base + t * D_] = s;
    }
    g_carry[(b * NCH_ + c) * D_ + d] = s;
}

// latency-optimized: batch all 64 loads (MLP=64), then serial FMA chain in regs
__global__ __launch_bounds__(256) void k_scan_combine() {
    int idx = blockIdx.x * blockDim.x + threadIdx.x;   // [0, B*D)
    int b = idx / D_;
    int d = idx % D_;
    float lam = g_lam[d >> 6];
    float lamL = pow_int(lam, L_);
    int base = b * NCH_ * D_ + d;

    float v[NCH_];
    #pragma unroll
    for (int c = 0; c < NCH_; c++) v[c] = g_carry[base + c * D_];

    float P = 0.0f;
    #pragma unroll
    for (int c = 0; c < NCH_; c++) {
        P = fmaf(lamL, P, v[c]);
        v[c] = P;
    }
    #pragma unroll
    for (int c = 0; c < NCH_; c++) g_carry[base + c * D_] = v[c];
}

__global__ __launch_bounds__(256) void k_fix_norm(const float* __restrict__ norm_weight) {
    int tok = blockIdx.x;
    int b = tok / N_;
    int n = tok % N_;
    int chunk = n >> 6;
    int tl = n & (L_ - 1);
    int tid = threadIdx.x;
    int d0 = tid * 4;
    int h = d0 >> 6;

    float lam = g_lam[h];
    float ch  = g_c[h];

    float4 v = *(const float4*)&g_o[(size_t)tok * D_ + d0];
    if (chunk > 0) {
        float lp = pow_int(lam, tl + 1);
        float4 cr = *(const float4*)&g_carry[(b * NCH_ + (chunk - 1)) * D_ + d0];
        v.x = fmaf(lp, cr.x, v.x);
        v.y = fmaf(lp, cr.y, v.y);
        v.z = fmaf(lp, cr.z, v.z);
        v.w = fmaf(lp, cr.w, v.w);
    }
    v.x *= ch; v.y *= ch; v.z *= ch; v.w *= ch;

    float ss = v.x * v.x + v.y * v.y + v.z * v.z + v.w * v.w;
    #pragma unroll
    for (int o = 16; o > 0; o >>= 1) ss += __shfl_xor_sync(0xFFFFFFFFu, ss, o);

    __shared__ float red[8];
    __shared__ float s_rstd;
    int lane = tid & 31, wid = tid >> 5;
    if (lane == 0) red[wid] = ss;
    __syncthreads();
    if (tid == 0) {
        float t = 0.0f;
        #pragma unroll
        for (int i = 0; i < 8; i++) t += red[i];
        s_rstd = rsqrtf(t * (1.0f / (float)D_) + 1e-6f);
    }
    __syncthreads();
    float rstd = s_rstd;

    float4 w = *(const float4*)&norm_weight[d0];
    float a0 = v.x * rstd * w.x, a1 = v.y * rstd * w.y;
    float a2 = v.z * rstd * w.z, a3 = v.w * rstd * w.w;

    __nv_bfloat16 h0 = __float2bfloat16(a0), h1 = __float2bfloat16(a1);
    __nv_bfloat16 h2 = __float2bfloat16(a2), h3 = __float2bfloat16(a3);
    __nv_bfloat16 l0 = __float2bfloat16(a0 - __bfloat162float(h0));
    __nv_bfloat16 l1 = __float2bfloat16(a1 - __bfloat162float(h1));
    __nv_bfloat16 l2 = __float2bfloat16(a2 - __bfloat162float(h2));
    __nv_bfloat16 l3 = __float2bfloat16(a3 - __bfloat162float(h3));

    size_t off = (size_t)tok * D_ + d0;
    __nv_bfloat162 ph0; ph0.x = h0; ph0.y = h1;
    __nv_bfloat162 ph1; ph1.x = h2; ph1.y = h3;
    __nv_bfloat162 pl0; pl0.x = l0; pl0.y = l1;
    __nv_bfloat162 pl1; pl1.x = l2; pl1.y = l3;
    *(__nv_bfloat162*)&g_a_hi[off]     = ph0;
    *(__nv_bfloat162*)&g_a_hi[off + 2] = ph1;
    *(__nv_bfloat162*)&g_a_lo[off]     = pl0;
    *(__nv_bfloat162*)&g_a_lo[off + 2] = pl1;
}

__global__ __launch_bounds__(256) void k_prep_w(const float* __restrict__ w) {
    int idx = blockIdx.x * blockDim.x + threadIdx.x;
    size_t off = (size_t)idx * 4;
    float4 v = *(const float4*)&w[off];
    __nv_bfloat16 h0 = __float2bfloat16(v.x), h1 = __float2bfloat16(v.y);
    __nv_bfloat16 h2 = __float2bfloat16(v.z), h3 = __float2bfloat16(v.w);
    __nv_bfloat16 l0 = __float2bfloat16(v.x - __bfloat162float(h0));
    __nv_bfloat16 l1 = __float2bfloat16(v.y - __bfloat162float(h1));
    __nv_bfloat16 l2 = __float2bfloat16(v.z - __bfloat162float(h2));
    __nv_bfloat16 l3 = __float2bfloat16(v.w - __bfloat16\
2float(h3));
    __nv_bfloat162 ph0; ph0.x = h0; ph0.y = h1;
    __nv_bfloat162 ph1; ph1.x = h2; ph1.y = h3;
    __nv_bfloat162 pl0; pl0.x = l0; pl0.y = l1;
    __nv_bfloat162 pl1; pl1.x = l2; pl1.y = l3;
    *(__nv_bfloat162*)&g_w_hi[off]     = ph0;
    *(__nv_bfloat162*)&g_w_hi[off + 2] = ph1;
    *(__nv_bfloat162*)&g_w_lo[off]     = pl0;
    *(__nv_bfloat162*)&g_w_lo[off + 2] = pl1;
}

// ============================ HMMA GEMM ============================
// C = Ahi*Whi^T + Alo*Whi^T + Ahi*Wlo^T. Shared-stage version: per k0 load
// Ahi, Alo, Whi, Wlo once (64KB) and run all 3 products from it.
// CTA 128x128, BK=64, 8 warps (4 m-row x 2 n-col), warp tile 32x64.
#define GM 128
#define GN 128
#define KS 64
#define STG 3
#define NITER 16
#define TILE_B 16384                            // one 128x64 bf16 tile
#define STAGE_BYTES (4 * TILE_B)                // Ahi, Alo, Whi, Wlo
#define SMEM_GEMM_TOTAL (STG * STAGE_BYTES)     // 192KB

#define SMEM_SWZ(off) ((off) ^ (((off) >> 3) & 0x70))

__device__ __forceinline__ void load_stage(uint32_t smem_base, int round, int bm, int bn, int tid) {
    int k0 = round * KS;
    uint32_t st = smem_base + (round % STG) * STAGE_BYTES;
    // 4 tiles x 1024 16B-chunks = 4096 chunks, 16 per thread
    #pragma unroll
    for (int i = 0; i < 16; i++) {
        int idx = i * 256 + tid;               // [0, 4096)
        int tile = idx >> 10;                  // 0:Ahi 1:Alo 2:Whi 3:Wlo
        int c = idx & 1023;
        int r = c >> 3, kc = c & 7;
        const __nv_bfloat16* src;
        int row;
        if (tile == 0)      { src = g_a_hi; row = bm + r; }
        else if (tile == 1) { src = g_a_lo; row = bm + r; }
        else if (tile == 2) { src = g_w_hi; row = bn + r; }
        else                { src = g_w_lo; row = bn + r; }
        const __nv_bfloat16* g = src + (size_t)row * D_ + k0 + kc * 8;
        CP_ASYNC16(st + tile * TILE_B + SMEM_SWZ(r * 128 + kc * 16), g);
    }
}

__global__ __launch_bounds__(256, 1) void k_gemm_mma(float* __restrict__ C) {
    extern __shared__ char smem[];
    uint32_t sb = smem_u32(smem);
    const int tid  = threadIdx.x;
    const int wid  = tid >> 5;
    const int lane = tid & 31;
    const int wm   = wid >> 1;          // 0..3 (M)
    const int wn   = wid & 1;           // 0..1 (N)
    const int bm   = blockIdx.y * GM;
    const int bn   = blockIdx.x * GN;

    const int t7 = lane & 7;
    const int q  = lane >> 3;
    // A x4 matrices: (m0,k0),(m+8,k0),(m0,k8),(m+8,k8)
    const int a_row = wm * 32 + (q & 1) * 8 + t7;
    const int a_cq  = q >> 1;
    // B x4 matrices: (n0,k0),(n0,k8),(n+8,k0),(n+8,k8)
    const int b_row = wn * 64 + (q >> 1) * 8 + t7;
    const int b_cq  = q & 1;

    float acc[2][8][4];
    #pragma unroll
    for (int im = 0; im < 2; im++)
        #pragma unroll
        for (int j = 0; j < 8; j++)
            #pragma unroll
            for (int e = 0; e < 4; e++) acc[im][j][e] = 0.0f;

    #pragma unroll
    for (int r = 0; r < STG - 1; r++) { load_stage(sb, r, bm, bn, tid); CP_COMMIT(); }

    for (int i = 0; i < NITER; i++) {
        CP_WAIT1();
        __syncthreads();
        int j = i + STG - 1;
        if (j < NITER) load_stage(sb, j, bm, bn, tid);
        CP_COMMIT();

        uint32_t st = sb + (i % STG) * STAGE_BYTES;
        #pragma unroll
        for (int ks = 0; ks < 4; ks++) {
            uint32_t ah[2][4], al[2][4];
            #pragma unroll
            for (int im = 0; im < 2; im++) {
                uint32_t ro = (a_row + im * 16) * 128 + (((ks * 2 + a_cq) ^ t7) << 4);
                LDSM4(ah[im][0], ah[im][1], ah[im][2], ah[im][3], st + ro);
                LDSM4(al[im][0], al[im][1], al[im][2], al[im][3], st + TILE_B + ro);
            }
            uint32_t bh[8][2], bl[8][2];
            #pragma unroll
            for (int jj = 0; jj < 4; jj++) {
                uint32_t ro = (b_row + jj * 16) * 128 + (((ks * 2 + b_cq) ^ t7) << 4);
                LDSM4(bh[2*jj][0], bh[2*jj][1], bh[2*jj+1][0], bh[2*jj+1][1], st + 2 * TILE_B + ro);
                LDSM4(bl[2*jj][0], bl[2*jj][1], bl[2*jj+1][0], bl[2*jj+1][1], st + 3 * TILE_B + ro);
            }
            #pragma unroll
            for (int im = 0; im < 2; im++)
                #pragma unroll
                for (int jt = 0; jt < 8; jt++) {
                    MMA_BF16(acc[im][jt], ah[im], bh[jt]);   // hi*hi
                    MMA_BF16(acc[im][jt], al[im], bh[jt]);   // lo*hi
                    MMA_BF16(acc[im][jt], ah[im], bl[jt]);   // hi*lo
                }
        }
    }

    #pragma unroll
    for (int im = 0; im < 2; im++) {
        int r0 = bm + wm * 32 + im * 16 + (lane >> 2);
        #pragma unroll
        for (int jt = 0; jt < 8; jt++) {
            int c = bn + wn * 64 + jt * 8 + (lane & 3) * 2;
            *(float2*)&C[(size_t)r0 * D_ + c]       = make_float2(acc[im][jt][0], acc[im][jt][1]);
            *(float2*)&C[(size_t)(r0 + 8) * D_ + c] = make_float2(acc[im][jt][2], acc[im][jt][3]);
        }
    }
}

// ============================ launch ============================
extern "C" void kernel_launch(void* const* d_in, const int* in_sizes, int n_in,
                              void* d_out, int out_size) {
    const float* x           = (const float*)d_in[0];
    const float* q           = (const float*)d_in[1];
    const float* k           = (const float*)d_in[2];
    const float* log_decay   = (const float*)d_in[3];
    const float* norm_weight = (const float*)d_in[4];
    const float* o_w         = (const float*)d_in[5];
    float* out = (float*)d_out;

    k_init<<<1, 32>>>(q, k, log_decay);
    k_prep_w<<<(D_ * D_ / 4) / 256, 256>>>(o_w);
    k_scan_local<<<B_ * NCH_, 1024>>>(x);
    k_scan_combine<<<(B_ * D_) / 256, 256>>>();
    k_fix_norm<<<M_, 256>>>(norm_weight);

    cudaFuncSetAttribute(k_gemm_mma, cudaFuncAttributeMaxDynamicSharedMemorySize,
                         SMEM_GEMM_TOTAL);
    dim3 grid(D_ / GN, M_ / GM);
    k_gemm_mma<<<grid, 256, SMEM_GEMM_TOTAL>>>(out);
}

// round 5
// speedup vs baseline: 3.8770x; 1.3101x over previous
#include <cuda_runtime.h>
#include <cuda_fp16.h>
#include <cstdint>

// Problem constants
#define B_   4
#define N_   4096
#define D_   1024
#define H_   16
#define DH_  64
#define L_   64
#define NCH_ (N_ / L_)
#define M_   (B_ * N_)           // 16384 tokens

// Scratch (__device__ globals; no allocation allowed)
__device__ float g_o[B_ * N_ * D_];
__device__ float g_carry[B_ * NCH_ * D_];
__device__ float g_lam[H_];
__device__ float g_c[H_];
__device__ __half g_a[M_ * D_];              // fp16 activations
__device__ __half g_w_hi[D_ * D_];           // o_w fp16 split
__device__ __half g_w_lo[D_ * D_];

__device__ __forceinline__ float pow_int(float base, int e) {
    float p = 1.0f, b = base;
    while (e) { if (e & 1) p *= b; b *= b; e >>= 1; }
    return p;
}

__device__ __forceinline__ uint32_t smem_u32(const void* p) {
    uint32_t a;
    asm("{ .reg .u64 t; cvta.to.shared.u64 t, %1; cvt.u32.u64 %0, t; }" : "=r"(a) : "l"(p));
    return a;
}

#define CP_ASYNC16(dst, src) \
    asm volatile("cp.async.cg.shared.global [%0], [%1], 16;" :: "r"(dst), "l"(src) : "memory")
#define CP_COMMIT() asm volatile("cp.async.commit_group;" ::: "memory")
#define CP_WAIT2()  asm volatile("cp.async.wait_group 2;" ::: "memory")

#define LDSM4(r0, r1, r2, r3, addr) \
    asm volatile("ldmatrix.sync.aligned.m8n8.x4.shared.b16 {%0,%1,%2,%3}, [%4];" \
                 : "=r"(r0), "=r"(r1), "=r"(r2), "=r"(r3) : "r"(addr))

#define MMA_F16(d, a, b) \
    asm volatile("mma.sync.aligned.m16n8k16.row.col.f32.f16.f16.f32 " \
                 "{%0,%1,%2,%3}, {%4,%5,%6,%7}, {%8,%9}, {%0,%1,%2,%3};" \
                 : "+f"((d)[0]), "+f"((d)[1]), "+f"((d)[2]), "+f"((d)[3]) \
                 : "r"((a)[0]), "r"((a)[1]), "r"((a)[2]), "r"((a)[3]), \
                   "r"((b)[0]), "r"((b)[1]))

// ============================ scan phases ============================
__global__ void k_init(const float* __restrict__ q, const float* __restrict__ k,
                       const float* __restrict__ log_decay) {
    int h = threadIdx.x;
    if (h >= H_) return;
    float a = log_decay[h];
    g_lam[h] = 1.0f / (1.0f + expf(-a));
    float c = 0.0f;
    const float* qh = q + h * DH_;
    const float* kh = k + h * DH_;
    #pragma unroll 16
    for (int j = 0; j < DH_; j++) c += qh[j] * kh[j];
    g_c[h] = c;
}

__global__ __launch_bounds__(1024) void k_scan_local(const float* __restrict__ x) {
    int blk = blockIdx.x;
    int b = blk / NCH_;
    int c = blk % NCH_;
    int d = threadIdx.x;
    float lam = g_lam[d >> 6];
    int base = (b * N_ + c * L_) * D_ + d;
    float s = 0.0f;
    #pragma unroll 8
    for (int t = 0; t < L_; t++) {
        s = fmaf(lam, s, x[base + t * D_]);
        g_o[base + t * D_] = s;
    }
    g_carry[(b * NCH_ + c) * D_ + d] = s;
}

__global__ __launch_bounds__(256) void k_scan_combine() {
    int idx = blockIdx.x * blockDim.x + threadIdx.x;   // [0, B*D)
    int b = idx / D_;
    int d = idx % D_;
    float lam = g_lam[d >> 6];
    float lamL = pow_int(lam, L_);
    int base = b * NCH_ * D_ + d;

    float v[NCH_];
    #pragma unroll
    for (int c = 0; c < NCH_; c++) v[c] = g_carry[base + c * D_];

    float P = 0.0f;
    #pragma unroll
    for (int c = 0; c < NCH_; c++) {
        P = fmaf(lamL, P, v[c]);
        v[c] = P;
    }
    #pragma unroll
    for (int c = 0; c < NCH_; c++) g_carry[base + c * D_] = v[c];
}

__global__ __launch_bounds__(256) void k_fix_norm(const float* __restrict__ norm_weight) {
    int tok = blockIdx.x;
    int b = tok / N_;
    int n = tok % N_;
    int chunk = n >> 6;
    int tl = n & (L_ - 1);
    int tid = threadIdx.x;
    int d0 = tid * 4;
    int h = d0 >> 6;

    float lam = g_lam[h];
    float ch  = g_c[h];

    float4 v = *(const float4*)&g_o[(size_t)tok * D_ + d0];
    if (chunk > 0) {
        float lp = pow_int(lam, tl + 1);
        float4 cr = *(const float4*)&g_carry[(b * NCH_ + (chunk - 1)) * D_ + d0];
        v.x = fmaf(lp, cr.x, v.x);
        v.y = fmaf(lp, cr.y, v.y);
        v.z = fmaf(lp, cr.z, v.z);
        v.w = fmaf(lp, cr.w, v.w);
    }
    v.x *= ch; v.y *= ch; v.z *= ch; v.w *= ch;

    float ss = v.x * v.x + v.y * v.y + v.z * v.z + v.w * v.w;
    #pragma unroll
    for (int o = 16; o > 0; o >>= 1) ss += __shfl_xor_sync(0xFFFFFFFFu, ss, o);

    __shared__ float red[8];
    __shared__ float s_rstd;
    int lane = tid & 31, wid = tid >> 5;
    if (lane == 0) red[wid] = ss;
    __syncthreads();
    if (tid == 0) {
        float t = 0.0f;
        #pragma unroll
        for (int i = 0; i < 8; i++) t += red[i];
        s_rstd = rsqrtf(t * (1.0f / (float)D_) + 1e-6f);
    }
    __syncthreads();
    float rstd = s_rstd;

    float4 w = *(const float4*)&norm_weight[d0];
    __half2 p0 = __floats2half2_rn(v.x * rstd * w.x, v.y * rstd * w.y);
    __half2 p1 = __floats2half2_rn(v.z * rstd * w.z, v.w * rstd * w.w);

    size_t off = (size_t)tok * D_ + d0;
    *(__half2*)&g_a[off]     = p0;
    *(__half2*)&g_a[off + 2] = p1;
}

__global__ __launch_bounds__(256) void k_prep_w(const float* __restrict__ w) {
    int idx = blockIdx.x * blockDim.x + threadIdx.x;
    size_t off = (size_t)idx * 4;
    float4 v = *(const float4*)&w[off];
    __half h0 = __float2half_rn(v.x), h1 = __float2half_rn(v.y);
    __half h2 = __float2half_rn(v.z), h3 = __float2half_rn(v.w);
    __half l0 = __float2half_rn(v.x - __half2float(h0));
    __half l1 = __float2half_rn(v.y - __half2float(h1));
    __half l2 = __float2half_rn(v.z - __half2float(h2));
    __half l3 = __float2half_rn(v.w - __half2float(h3));
    __half2 ph0; ph0.x = h0; ph0.y = h1;
    __half2 ph1; ph1.x = h2; ph1.y = h3;
    __half2 pl0; pl0.x = l0; pl0.y = l1;
    __half2 pl1; pl1.x = l2; pl1.y = l3;
    *(__half2*)&g_w_hi[off]     = ph0;
    *(__half2*)&g_w_hi[off + 2] = ph1;
    *(__half2*)&g_w_lo[off]     = pl0;
    *(__half2*)&g_w_lo[off + 2] = pl1;
}

// ============================ HMMA GEMM ============================
// C = A * (Whi + Wlo)^T, fp16 operands, fp32 accum. 2 products per k-slice.
// CTA 128x128, BK=64, 8 warps (4 m-row x 2 n-col), warp tile 32x64.
#define GM 128
#define GN 128
#define KS 64
#define STG 4
#define NITER 16
#define TILE_B 16384                            // one 128x64 fp16 tile
#define STAGE_BYTES (3 * TILE_B)                // A, Whi, Wlo = 48KB
#define SMEM_GEMM_TOTAL (STG * STAGE_BYTES)     // 192KB

#define SMEM_SWZ(off) ((off) ^ (((off) >> 3) & 0x70))

__device__ __forceinline__ void load_stage(uint32_t smem_base, int round, int bm, int bn, int tid) {
    int k0 = round * KS;
    uint32_t st = smem_base + (round & (STG - 1)) * STAGE_BYTES;
    // 3 tiles x 1024 16B-chunks = 3072 chunks, 12 per thread
    #pragma unroll
    for (int i = 0; i < 12; i++) {
        int idx = i * 256 + tid;               // [0, 3072)
        int tile = idx >> 10;                  // 0:A 1:Whi 2:Wlo
        int c = idx & 1023;
        int r = c >> 3, kc = c & 7;
        const __half* src;
        int row;
        if (tile == 0)      { src = g_a;    row = bm + r; }
        else if (tile == 1) { src = g_w_hi; row = bn + r; }
        else                { src = g_w_lo; row = bn + r; }
        const __half* g = src + (size_t)row * D_ + k0 + kc * 8;
        CP_ASYNC16(st + tile * TILE_B + SMEM_SWZ(r * 128 + kc * 16), g);
    }
}

__global__ __launch_bounds__(256, 1) void k_gemm_mma(float* __restrict__ C) {
    extern __shared__ char smem[];
    uint32_t sb = smem_u32(smem);
    const int tid  = threadIdx.x;
    const int wid  = tid >> 5;
    const int lane = tid & 31;
    const int wm   = wid >> 1;          // 0..3 (M)
    const int wn   = wid & 1;           // 0..1 (N)
    const int bm   = blockIdx.y * GM;
    const int bn   = blockIdx.x * GN;

    const int t7 = lane & 7;
    const int q  = lane >> 3;
    // A x4 matrices: (m0,k0),(m+8,k0),(m0,k8),(m+8,k8)
    const int a_row = wm * 32 + (q & 1) * 8 + t7;
    const int a_cq  = q >> 1;
    // B x4 matrices: (n0,k0),(n0,k8),(n+8,k0),(n+8,k8)
    const int b_row = wn * 64 + (q >> 1) * 8 + t7;
    const int b_cq  = q & 1;

    float acc[2][8][4];
    #pragma unroll
    for (int im = 0; im < 2; im++)
        #pragma unroll
        for (int j = 0; j < 8; j++)
            #pragma unroll
            for (int e = 0; e < 4; e++) acc[im][j][e] = 0.0f;

    #pragma unroll
    for (int r = 0; r < STG - 1; r++) { load_stage(sb, r, bm, bn, tid); CP_COMMIT(); }

    for (int i = 0; i < NITER; i++) {
        CP_WAIT2();
        __syncthreads();
        int j = i + STG - 1;
        if (j < NITER) load_stage(sb, j, bm, bn, tid);
        CP_COMMIT();

        uint32_t st = sb + (i & (STG - 1)) * STAGE_BYTES;
        #pragma unroll
        for (int ks = 0; ks < 4; ks++) {
            uint32_t af[2][4];
            #pragma unroll
            for (int im = 0; im < 2; im++) {
                uint32_t ro = (a_row + im * 16) * 128 + (((ks * 2 + a_cq) ^ t7) << 4);
                LDSM4(af[im][0], af[im][1], af[im][2], af[im][3], st + ro);
            }
            uint32_t bh[8][2], bl[8][2];
            #pragma unroll
            for (int jj = 0; jj < 4; jj++) {
                uint32_t ro = (b_row + jj * 16) * 128 + (((ks * 2 + b_cq) ^ t7) << 4);
                LDSM4(bh[2*jj][0], bh[2*jj][1], bh[2*jj+1][0], bh[2*jj+1][1], st + TILE_B + ro);
                LDSM4(bl[2*jj][0], bl[2*jj][1], bl[2*jj+1][0], bl[2*jj+1][1], st + 2 * TILE_B + ro);
            }
            #pragma unroll
            for (int im = 0; im < 2; im++)
                #pragma unroll
                for (int jt = 0; jt < 8; jt++) {
                    MMA_F16(acc[im][jt], af[im], bh[jt]);   // A * Whi
                    MMA_F16(acc[im][jt], af[im], bl[jt]);   // A * Wlo
                }
        }
    }

    #pragma unroll
    for (int im = 0; im < 2; im++) {
        int r0 = bm + wm * 32 + im * 16 + (lane >> 2);
        #pragma unroll
        for (int jt = 0; jt < 8; jt++) {
            int c = bn + wn * 64 + jt * 8 + (lane & 3) * 2;
            *(float2*)&C[(size_t)r0 * D_ + c]       = make_float2(acc[im][jt][0], acc[im][jt][1]);
            *(float2*)&C[(size_t)(r0 + 8) * D_ + c] = make_float2(acc[im][jt][2], acc[im][jt][3]);
        }
    }
}

// ============================ launch ============================
extern "C" void kernel_launch(void* const* d_in, const int* in_sizes, int n_in,
                              void* d_out, int out_size) {
    const float* x           = (const float*)d_in[0];
    const float* q           = (const float*)d_in[1];
    const float* k           = (const float*)d_in[2];
    const float* log_decay   = (const float*)d_in[3];
    const float* norm_weight = (const float*)d_in[4];
    const float* o_w         = (const float*)d_in[5];
    float* out = (float*)d_out;

    k_init<<<1, 32>>>(q, k, log_decay);
    k_prep_w<<<(D_ * D_ / 4) / 256, 256>>>(o_w);
    k_scan_local<<<B_ * NCH_, 1024>>>(x);
    k_scan_combine<<<(B_ * D_) / 256, 256>>>();
    k_fix_norm<<<M_, 256>>>(norm_weight);

    cudaFuncSetAttribute(k_gemm_mma, cudaFuncAttributeMaxDynamicSharedMemorySize,
                         SMEM_GEMM_TOTAL);
    dim3 grid(D_ / GN, M_ / GM);
    k_gemm_mma<<<grid, 256, SMEM_GEMM_TOTAL>>>(out);
}